// round 1
// baseline (speedup 1.0000x reference)
#include <cuda_runtime.h>
#include <math.h>

#define BATCH 4096
#define TT    16
#define HH    256
#define FF    256
#define ZZ    128
#define PP    10
#define PREV_ 5

// ---------------- scratch (device globals; no runtime allocation) ----------------
__device__ float g_Wg[896 * 1024];    // [W_lstm ; U_lstm]
__device__ float g_Wq[1024 * 256];    // [W4 | W7 padded]
__device__ float g_Wml[256 * 512];    // blockdiag([W5|W6],[W8|W9])
__device__ float g_bq[256];
__device__ float g_bml[512];
__device__ float g_Xg[BATCH * 896];
__device__ float g_gates[BATCH * 1024];
__device__ float g_Xq[BATCH * 1024];
__device__ float g_c[BATCH * HH];
__device__ float g_h[BATCH * HH];
__device__ float g_hraw[BATCH * HH];
__device__ float g_y1[BATCH * FF];
__device__ float g_y2[BATCH * FF];
__device__ float g_ybuf[2 * BATCH * FF];
__device__ float g_zbuf[2 * BATCH * ZZ];
__device__ float g_HZ[BATCH * 256];
__device__ float g_ML[BATCH * 512];
__device__ float g_lam[PP * BATCH];

// ---------------- SGEMM: C = act(A(4096xK) @ W(KxN) + bias) ----------------
// BM=64, BN=128, BK=16, TM=4, TN=8, 256 threads. M fixed = 4096.
__global__ __launch_bounds__(256) void sgemm_bias_act(
    const float* __restrict__ A, const float* __restrict__ W,
    const float* __restrict__ bias, float* __restrict__ C,
    int K, int N, int do_relu)
{
    const int BM = 64, BN = 128, BK = 16, TM = 4, TN = 8;
    __shared__ float As[BK][BM];
    __shared__ float Ws[BK][BN];

    int tid  = threadIdx.x;
    int row0 = blockIdx.x * BM;
    int col0 = blockIdx.y * BN;
    int trow = tid >> 4;   // 0..15
    int tcol = tid & 15;   // 0..15

    float acc[TM][TN];
#pragma unroll
    for (int i = 0; i < TM; i++)
#pragma unroll
        for (int j = 0; j < TN; j++) acc[i][j] = 0.f;

    int a_r = tid >> 2;           // 0..63
    int a_c = (tid & 3) << 2;     // 0,4,8,12
    int w_r = tid >> 5;           // 0..7
    int w_c = (tid & 31) << 2;    // 0..124

    const float* Aptr = A + (size_t)(row0 + a_r) * K + a_c;
    const float* Wptr = W + (size_t)w_r * N + col0 + w_c;

    for (int kt = 0; kt < K; kt += BK) {
        float4 av = *(const float4*)(Aptr + kt);
        As[a_c + 0][a_r] = av.x;
        As[a_c + 1][a_r] = av.y;
        As[a_c + 2][a_r] = av.z;
        As[a_c + 3][a_r] = av.w;
        float4 wv0 = *(const float4*)(Wptr + (size_t)kt * N);
        float4 wv1 = *(const float4*)(Wptr + (size_t)(kt + 8) * N);
        *(float4*)&Ws[w_r][w_c]     = wv0;
        *(float4*)&Ws[w_r + 8][w_c] = wv1;
        __syncthreads();
#pragma unroll
        for (int k = 0; k < BK; k++) {
            float4 af  = *(const float4*)&As[k][trow * TM];
            float4 wf0 = *(const float4*)&Ws[k][tcol * 4];
            float4 wf1 = *(const float4*)&Ws[k][64 + tcol * 4];
            float ar[TM] = {af.x, af.y, af.z, af.w};
            float wr[TN] = {wf0.x, wf0.y, wf0.z, wf0.w, wf1.x, wf1.y, wf1.z, wf1.w};
#pragma unroll
            for (int i = 0; i < TM; i++)
#pragma unroll
                for (int j = 0; j < TN; j++) acc[i][j] = fmaf(ar[i], wr[j], acc[i][j]);
        }
        __syncthreads();
    }

#pragma unroll
    for (int i = 0; i < TM; i++) {
        int r = row0 + trow * TM + i;
#pragma unroll
        for (int j = 0; j < TN; j++) {
            int cc = (j < 4) ? (tcol * 4 + j) : (64 + tcol * 4 + (j - 4));
            int cN = col0 + cc;
            float v = acc[i][j] + bias[cN];
            if (do_relu) v = fmaxf(v, 0.f);
            C[(size_t)r * N + cN] = v;
        }
    }
}

// ---------------- setup kernels ----------------
__global__ void init_state()
{
    int i = blockIdx.x * blockDim.x + threadIdx.x;
    if (i < BATCH * HH) { g_c[i] = 0.f; g_h[i] = 0.f; }
    if (i < BATCH * FF) g_ybuf[i] = 0.f;       // ping buffer 0
    if (i < BATCH * ZZ) g_zbuf[i] = 0.f;       // ping buffer 0
}

__global__ void build_weights(
    const float* __restrict__ W_lstm, const float* __restrict__ U_lstm,
    const float* __restrict__ W4, const float* __restrict__ W7,
    const float* __restrict__ W5, const float* __restrict__ W6,
    const float* __restrict__ W8, const float* __restrict__ W9,
    const float* __restrict__ b4, const float* __restrict__ b7,
    const float* __restrict__ b5, const float* __restrict__ b6,
    const float* __restrict__ b8, const float* __restrict__ b9)
{
    int i = blockIdx.x * blockDim.x + threadIdx.x;
    if (i < 896 * 1024) {
        int r = i >> 10, c = i & 1023;
        g_Wg[i] = (r < 640) ? W_lstm[i] : U_lstm[((r - 640) << 10) + c];
    }
    if (i < 1024 * 256) {
        int r = i >> 8, c = i & 255;
        float v;
        if (c < 128) v = W4[(r << 7) + c];
        else {
            int cc = c - 128;
            if (r < 512)      v = W7[(r << 7) + cc];
            else if (r < 768) v = 0.f;
            else              v = W7[((r - 256) << 7) + cc];
        }
        g_Wq[i] = v;
    }
    if (i < 256 * 512) {
        int r = i >> 9, c = i & 511;
        float v = 0.f;
        if (r < 128) {
            if (c < 128)      v = W5[(r << 7) + c];
            else if (c < 256) v = W6[(r << 7) + (c - 128)];
        } else {
            int rr = r - 128;
            if (c >= 256 && c < 384) v = W8[(rr << 7) + (c - 256)];
            else if (c >= 384)       v = W9[(rr << 7) + (c - 384)];
        }
        g_Wml[i] = v;
    }
    if (i < 256) g_bq[i] = (i < 128) ? b4[i] : b7[i - 128];
    if (i < 512) {
        float v;
        if (i < 128)      v = b5[i];
        else if (i < 256) v = b6[i - 128];
        else if (i < 384) v = b8[i - 256];
        else              v = b9[i - 384];
        g_bml[i] = v;
    }
}

__global__ void time_feat(const float* __restrict__ t,
                          const float* __restrict__ alpha,
                          const float* __restrict__ beta,
                          const float* __restrict__ base,
                          float* __restrict__ out_prob)
{
    int b = blockIdx.x * blockDim.x + threadIdx.x;
    if (b >= BATCH) return;
    float al = *alpha, be = *beta, ba = *base;
    float tv[TT];
#pragma unroll
    for (int i = 0; i < TT; i++) tv[i] = t[b * TT + i];
#pragma unroll
    for (int j = 0; j < PP; j++) {
        int cti = PREV_ + j;
        float ct = tv[cti], last = tv[cti - 1];
        float tk = 0.f, td = 0.f;
        for (int i = 0; i < cti; i++) {
            tk += expf(be * (tv[i] - ct));
            td += expf(be * (tv[i] - last));
        }
        float lm = ba + al * tk;
        g_lam[j * BATCH + b] = lm;
        out_prob[j * BATCH + b] = lm * expf((last - ct) * ba + (al / be) * (tk - td));
    }
}

// ---------------- per-step kernels ----------------
__global__ void build_Xg(const float* __restrict__ zprev,
                         const float* __restrict__ hi,
                         const float* __restrict__ yprev)
{
    int i = blockIdx.x * blockDim.x + threadIdx.x;
    if (i >= BATCH * 896) return;
    int b = i / 896, c = i % 896;
    float v;
    if (c < 128)       v = zprev[(b << 7) + c];
    else if (c < 384)  v = hi[(b << 8) + (c - 128)];
    else if (c < 640)  v = yprev[(b << 8) + (c - 384)];
    else               v = g_h[(b << 8) + (c - 640)];
    g_Xg[i] = v;
}

__device__ __forceinline__ float sigm(float x) { return 1.f / (1.f + expf(-x)); }

__global__ void lstm_pw(int j)
{
    int i = blockIdx.x * blockDim.x + threadIdx.x;
    if (i >= BATCH * HH) return;
    int b = i >> 8, k = i & 255;
    const float* g = g_gates + ((size_t)b << 10);
    float gi = g[k], gf = g[HH + k], gg = g[2 * HH + k], go = g[3 * HH + k];
    float cv = sigm(gf) * g_c[i] + sigm(gi) * tanhf(gg);
    g_c[i] = cv;
    float hr = sigm(go) * tanhf(cv);
    g_hraw[i] = hr;
    g_h[i] = g_lam[j * BATCH + b] * hr;
}

__global__ void copy_y_out(const float* __restrict__ y, float* __restrict__ out_ys, int j)
{
    int i = blockIdx.x * blockDim.x + threadIdx.x;
    if (i >= BATCH * FF) return;
    int b = i >> 8, f = i & 255;
    out_ys[((size_t)b * PP + j) * FF + f] = y[i];
}

__global__ void build_Xq(const float* __restrict__ hi,
                         const float* __restrict__ ycur,
                         const float* __restrict__ yprev)
{
    int i = blockIdx.x * blockDim.x + threadIdx.x;
    if (i >= BATCH * 1024) return;
    int b = i >> 10, c = i & 1023;
    float v;
    if (c < 256)       v = hi[(b << 8) + c];
    else if (c < 512)  v = g_hraw[(b << 8) + (c - 256)];
    else if (c < 768)  v = ycur[(b << 8) + (c - 512)];
    else               v = yprev[(b << 8) + (c - 768)];
    g_Xq[i] = v;
}

__global__ void sample_out(const float* __restrict__ npost,
                           const float* __restrict__ nprior,
                           float* __restrict__ znext,
                           float* __restrict__ out_mpost, float* __restrict__ out_lvpost,
                           float* __restrict__ out_mprior, float* __restrict__ out_lvprior,
                           float* __restrict__ out_zpost, float* __restrict__ out_zprior,
                           int j)
{
    int i = blockIdx.x * blockDim.x + threadIdx.x;
    if (i >= BATCH * ZZ) return;
    int b = i >> 7, z = i & 127;
    const float* r = g_ML + ((size_t)b << 9);
    float mj = r[z], lj = r[ZZ + z], mp = r[2 * ZZ + z], lp = r[3 * ZZ + z];
    float zj = mj + npost[i] * expf(0.5f * lj);
    float zp = mp + nprior[i] * expf(0.5f * lp);
    size_t o1 = ((size_t)b * PP + j) * ZZ + z;
    out_mpost[o1] = mj; out_lvpost[o1] = lj;
    out_mprior[o1] = mp; out_lvprior[o1] = lp;
    size_t o2 = (size_t)j * BATCH * ZZ + i;
    out_zpost[o2] = zj; out_zprior[o2] = zp;
    znext[i] = zj;
}

// ---------------- host launch ----------------
extern "C" void kernel_launch(void* const* d_in, const int* in_sizes, int n_in,
                              void* d_out, int out_size)
{
    (void)in_sizes; (void)n_in; (void)out_size;
    const float* h_i    = (const float*)d_in[0];
    const float* inpt   = (const float*)d_in[1];
    const float* npost  = (const float*)d_in[2];
    const float* nprior = (const float*)d_in[3];
    const float* W_lstm = (const float*)d_in[4];
    const float* U_lstm = (const float*)d_in[5];
    const float* b_lstm = (const float*)d_in[6];
    const float* W1 = (const float*)d_in[7];  const float* b1 = (const float*)d_in[8];
    const float* W2 = (const float*)d_in[9];  const float* b2 = (const float*)d_in[10];
    const float* W3 = (const float*)d_in[11]; const float* b3 = (const float*)d_in[12];
    const float* W4 = (const float*)d_in[13]; const float* b4 = (const float*)d_in[14];
    const float* W5 = (const float*)d_in[15]; const float* b5 = (const float*)d_in[16];
    const float* W6 = (const float*)d_in[17]; const float* b6 = (const float*)d_in[18];
    const float* W7 = (const float*)d_in[19]; const float* b7 = (const float*)d_in[20];
    const float* W8 = (const float*)d_in[21]; const float* b8 = (const float*)d_in[22];
    const float* W9 = (const float*)d_in[23]; const float* b9 = (const float*)d_in[24];
    const float* alpha = (const float*)d_in[25];
    const float* beta  = (const float*)d_in[26];
    const float* base  = (const float*)d_in[27];

    float* out = (float*)d_out;
    float* out_ys      = out;
    float* out_mpost   = out_ys + (size_t)BATCH * PP * FF;
    float* out_lvpost  = out_mpost  + (size_t)BATCH * PP * ZZ;
    float* out_mprior  = out_lvpost + (size_t)BATCH * PP * ZZ;
    float* out_lvprior = out_mprior + (size_t)BATCH * PP * ZZ;
    float* out_zpost   = out_lvprior + (size_t)BATCH * PP * ZZ;
    float* out_zprior  = out_zpost + (size_t)PP * BATCH * ZZ;
    float* out_prob    = out_zprior + (size_t)PP * BATCH * ZZ;

    float *p_Xg, *p_Wg, *p_gates, *p_Xq, *p_Wq, *p_bq, *p_HZ, *p_Wml, *p_bml,
          *p_ML, *p_hraw, *p_y1, *p_y2, *p_ybuf, *p_zbuf;
    cudaGetSymbolAddress((void**)&p_Xg, g_Xg);
    cudaGetSymbolAddress((void**)&p_Wg, g_Wg);
    cudaGetSymbolAddress((void**)&p_gates, g_gates);
    cudaGetSymbolAddress((void**)&p_Xq, g_Xq);
    cudaGetSymbolAddress((void**)&p_Wq, g_Wq);
    cudaGetSymbolAddress((void**)&p_bq, g_bq);
    cudaGetSymbolAddress((void**)&p_HZ, g_HZ);
    cudaGetSymbolAddress((void**)&p_Wml, g_Wml);
    cudaGetSymbolAddress((void**)&p_bml, g_bml);
    cudaGetSymbolAddress((void**)&p_ML, g_ML);
    cudaGetSymbolAddress((void**)&p_hraw, g_hraw);
    cudaGetSymbolAddress((void**)&p_y1, g_y1);
    cudaGetSymbolAddress((void**)&p_y2, g_y2);
    cudaGetSymbolAddress((void**)&p_ybuf, g_ybuf);
    cudaGetSymbolAddress((void**)&p_zbuf, g_zbuf);

    const int TPB = 256;
    init_state<<<(BATCH * HH + TPB - 1) / TPB, TPB>>>();
    build_weights<<<(896 * 1024 + TPB - 1) / TPB, TPB>>>(
        W_lstm, U_lstm, W4, W7, W5, W6, W8, W9, b4, b7, b5, b6, b8, b9);
    time_feat<<<(BATCH + TPB - 1) / TPB, TPB>>>(inpt, alpha, beta, base, out_prob);

    for (int j = 0; j < PP; j++) {
        int rd = j & 1, wr = 1 - rd;
        float* zprev = p_zbuf + (size_t)rd * BATCH * ZZ;
        float* znext = p_zbuf + (size_t)wr * BATCH * ZZ;
        float* yprev = p_ybuf + (size_t)rd * BATCH * FF;
        float* ycur  = p_ybuf + (size_t)wr * BATCH * FF;

        build_Xg<<<(BATCH * 896 + TPB - 1) / TPB, TPB>>>(zprev, h_i, yprev);
        sgemm_bias_act<<<dim3(64, 8), 256>>>(p_Xg, p_Wg, b_lstm, p_gates, 896, 1024, 0);
        lstm_pw<<<(BATCH * HH + TPB - 1) / TPB, TPB>>>(j);

        sgemm_bias_act<<<dim3(64, 2), 256>>>(p_hraw, W1, b1, p_y1, 256, 256, 1);
        sgemm_bias_act<<<dim3(64, 2), 256>>>(p_y1, W2, b2, p_y2, 256, 256, 1);
        sgemm_bias_act<<<dim3(64, 2), 256>>>(p_y2, W3, b3, ycur, 256, 256, 1);
        copy_y_out<<<(BATCH * FF + TPB - 1) / TPB, TPB>>>(ycur, out_ys, j);

        build_Xq<<<(BATCH * 1024 + TPB - 1) / TPB, TPB>>>(h_i, ycur, yprev);
        sgemm_bias_act<<<dim3(64, 2), 256>>>(p_Xq, p_Wq, p_bq, p_HZ, 1024, 256, 1);
        sgemm_bias_act<<<dim3(64, 4), 256>>>(p_HZ, p_Wml, p_bml, p_ML, 256, 512, 1);
        sample_out<<<(BATCH * ZZ + TPB - 1) / TPB, TPB>>>(
            npost + (size_t)j * BATCH * ZZ, nprior + (size_t)j * BATCH * ZZ,
            znext, out_mpost, out_lvpost, out_mprior, out_lvprior,
            out_zpost, out_zprior, j);
    }
}

// round 2
// speedup vs baseline: 1.2121x; 1.2121x over previous
#include <cuda_runtime.h>
#include <math.h>

#define BATCH 4096
#define TT    16
#define HH    256
#define FF    256
#define ZZ    128
#define PP    10
#define PREV_ 5

// ---------------- scratch (device globals; no runtime allocation) ----------------
__device__ float g_Wg[896 * 1024];    // [W_lstm ; U_lstm]
__device__ float g_Wq[1024 * 256];    // [W4 | W7 padded]
__device__ float g_Wml[256 * 512];    // blockdiag([W5|W6],[W8|W9])
__device__ float g_bq[256];
__device__ float g_bml[512];
__device__ float g_Xg[BATCH * 896];
__device__ float g_gates[BATCH * 1024];
__device__ float g_Xq[BATCH * 1024];
__device__ float g_c[BATCH * HH];
__device__ float g_h[BATCH * HH];
__device__ float g_hraw[BATCH * HH];
__device__ float g_y1[BATCH * FF];
__device__ float g_y2[BATCH * FF];
__device__ float g_ybuf[2 * BATCH * FF];
__device__ float g_zbuf[2 * BATCH * ZZ];
__device__ float g_HZ[BATCH * 256];
__device__ float g_ML[BATCH * 512];
__device__ float g_lam[PP * BATCH];

// ---------------- packed f32x2 helpers (Blackwell FFMA2 path) ----------------
__device__ __forceinline__ unsigned long long pack2(float x) {
    unsigned long long r;
    asm("mov.b64 %0, {%1, %1};" : "=l"(r) : "f"(x));
    return r;
}
__device__ __forceinline__ void ffma2(unsigned long long& d,
                                      unsigned long long a,
                                      unsigned long long b) {
    asm("fma.rn.f32x2 %0, %1, %2, %0;" : "+l"(d) : "l"(a), "l"(b));
}
__device__ __forceinline__ float2 unpack2(unsigned long long v) {
    float2 r;
    asm("mov.b64 {%0, %1}, %2;" : "=f"(r.x), "=f"(r.y) : "l"(v));
    return r;
}

// ---------------- SGEMM (FFMA2): C = act(A(MxK) @ W(KxN) + bias) ----------------
// BN=128, BK=16, 256 threads, TM = BM/16, TN=8 (4 packed pairs).
// Optional second output C2 (row-interleaved by step j) for fusing y copies.
template<int BM, int TM>
__global__ __launch_bounds__(256) void sgemm2(
    const float* __restrict__ A, const float* __restrict__ W,
    const float* __restrict__ bias, float* __restrict__ C,
    int K, int N, int do_relu,
    float* __restrict__ C2, int jj)
{
    __shared__ float As[16][BM];
    __shared__ float Ws[16][128];

    const int tid  = threadIdx.x;
    const int row0 = blockIdx.x * BM;
    const int col0 = blockIdx.y * 128;
    const int trow = tid >> 4;   // 0..15
    const int tcol = tid & 15;   // 0..15

    unsigned long long acc[TM][4];
#pragma unroll
    for (int i = 0; i < TM; i++)
#pragma unroll
        for (int j = 0; j < 4; j++) acc[i][j] = 0ULL;

    const int ALD = (BM * 16) / (256 * 4);   // float4 A-loads per thread

    for (int kt = 0; kt < K; kt += 16) {
#pragma unroll
        for (int l = 0; l < ALD; l++) {
            int idx = tid + l * 256;          // over BM x 4 float4 grid
            int ar  = idx >> 2;
            int ac  = (idx & 3) << 2;
            float4 v = *(const float4*)(A + (size_t)(row0 + ar) * K + kt + ac);
            As[ac + 0][ar] = v.x;
            As[ac + 1][ar] = v.y;
            As[ac + 2][ar] = v.z;
            As[ac + 3][ar] = v.w;
        }
#pragma unroll
        for (int l = 0; l < 2; l++) {
            int idx = tid + l * 256;          // over 16 x 32 float4 grid
            int wr  = idx >> 5;
            int wc  = (idx & 31) << 2;
            *(float4*)&Ws[wr][wc] =
                *(const float4*)(W + (size_t)(kt + wr) * N + col0 + wc);
        }
        __syncthreads();

#pragma unroll
        for (int k = 0; k < 16; k++) {
            float a[TM];
#pragma unroll
            for (int i = 0; i < TM; i += 4)
                *(float4*)&a[i] = *(const float4*)&As[k][trow * TM + i];
            ulonglong2 w0 = *(const ulonglong2*)&Ws[k][tcol * 4];
            ulonglong2 w1 = *(const ulonglong2*)&Ws[k][64 + tcol * 4];
#pragma unroll
            for (int i = 0; i < TM; i++) {
                unsigned long long ap = pack2(a[i]);
                ffma2(acc[i][0], ap, w0.x);
                ffma2(acc[i][1], ap, w0.y);
                ffma2(acc[i][2], ap, w1.x);
                ffma2(acc[i][3], ap, w1.y);
            }
        }
        __syncthreads();
    }

#pragma unroll
    for (int i = 0; i < TM; i++) {
        int r = row0 + trow * TM + i;
#pragma unroll
        for (int j = 0; j < 4; j++) {
            int cbase = col0 + ((j < 2) ? (tcol * 4 + 2 * j)
                                        : (64 + tcol * 4 + 2 * (j - 2)));
            float2 p = unpack2(acc[i][j]);
            p.x += bias[cbase];
            p.y += bias[cbase + 1];
            if (do_relu) { p.x = fmaxf(p.x, 0.f); p.y = fmaxf(p.y, 0.f); }
            *(float2*)&C[(size_t)r * N + cbase] = p;
            if (C2)
                *(float2*)&C2[((size_t)r * PP + jj) * N + cbase] = p;
        }
    }
}

// ---------------- setup kernels ----------------
__global__ void init_state()
{
    int i = blockIdx.x * blockDim.x + threadIdx.x;
    if (i < BATCH * HH) { g_c[i] = 0.f; g_h[i] = 0.f; }
    if (i < BATCH * FF) g_ybuf[i] = 0.f;       // ping buffer 0
    if (i < BATCH * ZZ) g_zbuf[i] = 0.f;       // ping buffer 0
}

__global__ void build_weights(
    const float* __restrict__ W_lstm, const float* __restrict__ U_lstm,
    const float* __restrict__ W4, const float* __restrict__ W7,
    const float* __restrict__ W5, const float* __restrict__ W6,
    const float* __restrict__ W8, const float* __restrict__ W9,
    const float* __restrict__ b4, const float* __restrict__ b7,
    const float* __restrict__ b5, const float* __restrict__ b6,
    const float* __restrict__ b8, const float* __restrict__ b9)
{
    int i = blockIdx.x * blockDim.x + threadIdx.x;
    if (i < 896 * 1024) {
        int r = i >> 10, c = i & 1023;
        g_Wg[i] = (r < 640) ? W_lstm[i] : U_lstm[((r - 640) << 10) + c];
    }
    if (i < 1024 * 256) {
        int r = i >> 8, c = i & 255;
        float v;
        if (c < 128) v = W4[(r << 7) + c];
        else {
            int cc = c - 128;
            if (r < 512)      v = W7[(r << 7) + cc];
            else if (r < 768) v = 0.f;
            else              v = W7[((r - 256) << 7) + cc];
        }
        g_Wq[i] = v;
    }
    if (i < 256 * 512) {
        int r = i >> 9, c = i & 511;
        float v = 0.f;
        if (r < 128) {
            if (c < 128)      v = W5[(r << 7) + c];
            else if (c < 256) v = W6[(r << 7) + (c - 128)];
        } else {
            int rr = r - 128;
            if (c >= 256 && c < 384) v = W8[(rr << 7) + (c - 256)];
            else if (c >= 384)       v = W9[(rr << 7) + (c - 384)];
        }
        g_Wml[i] = v;
    }
    if (i < 256) g_bq[i] = (i < 128) ? b4[i] : b7[i - 128];
    if (i < 512) {
        float v;
        if (i < 128)      v = b5[i];
        else if (i < 256) v = b6[i - 128];
        else if (i < 384) v = b8[i - 256];
        else              v = b9[i - 384];
        g_bml[i] = v;
    }
}

__global__ void time_feat(const float* __restrict__ t,
                          const float* __restrict__ alpha,
                          const float* __restrict__ beta,
                          const float* __restrict__ base,
                          float* __restrict__ out_prob)
{
    int b = blockIdx.x * blockDim.x + threadIdx.x;
    if (b >= BATCH) return;
    float al = *alpha, be = *beta, ba = *base;
    float tv[TT];
#pragma unroll
    for (int i = 0; i < TT; i++) tv[i] = t[b * TT + i];
#pragma unroll
    for (int j = 0; j < PP; j++) {
        int cti = PREV_ + j;
        float ct = tv[cti], last = tv[cti - 1];
        float tk = 0.f, td = 0.f;
        for (int i = 0; i < cti; i++) {
            tk += expf(be * (tv[i] - ct));
            td += expf(be * (tv[i] - last));
        }
        float lm = ba + al * tk;
        g_lam[j * BATCH + b] = lm;
        out_prob[j * BATCH + b] = lm * expf((last - ct) * ba + (al / be) * (tk - td));
    }
}

// ---------------- per-step kernels ----------------
__global__ void build_Xg(const float* __restrict__ zprev,
                         const float* __restrict__ hi,
                         const float* __restrict__ yprev)
{
    int i = blockIdx.x * blockDim.x + threadIdx.x;
    if (i >= BATCH * 896) return;
    int b = i / 896, c = i % 896;
    float v;
    if (c < 128)       v = zprev[(b << 7) + c];
    else if (c < 384)  v = hi[(b << 8) + (c - 128)];
    else if (c < 640)  v = yprev[(b << 8) + (c - 384)];
    else               v = g_h[(b << 8) + (c - 640)];
    g_Xg[i] = v;
}

__device__ __forceinline__ float sigm(float x) { return 1.f / (1.f + expf(-x)); }

__global__ void lstm_pw(int j)
{
    int i = blockIdx.x * blockDim.x + threadIdx.x;
    if (i >= BATCH * HH) return;
    int b = i >> 8, k = i & 255;
    const float* g = g_gates + ((size_t)b << 10);
    float gi = g[k], gf = g[HH + k], gg = g[2 * HH + k], go = g[3 * HH + k];
    float cv = sigm(gf) * g_c[i] + sigm(gi) * tanhf(gg);
    g_c[i] = cv;
    float hr = sigm(go) * tanhf(cv);
    g_hraw[i] = hr;
    g_h[i] = g_lam[j * BATCH + b] * hr;
}

__global__ void build_Xq(const float* __restrict__ hi,
                         const float* __restrict__ ycur,
                         const float* __restrict__ yprev)
{
    int i = blockIdx.x * blockDim.x + threadIdx.x;
    if (i >= BATCH * 1024) return;
    int b = i >> 10, c = i & 1023;
    float v;
    if (c < 256)       v = hi[(b << 8) + c];
    else if (c < 512)  v = g_hraw[(b << 8) + (c - 256)];
    else if (c < 768)  v = ycur[(b << 8) + (c - 512)];
    else               v = yprev[(b << 8) + (c - 768)];
    g_Xq[i] = v;
}

__global__ void sample_out(const float* __restrict__ npost,
                           const float* __restrict__ nprior,
                           float* __restrict__ znext,
                           float* __restrict__ out_mpost, float* __restrict__ out_lvpost,
                           float* __restrict__ out_mprior, float* __restrict__ out_lvprior,
                           float* __restrict__ out_zpost, float* __restrict__ out_zprior,
                           int j)
{
    int i = blockIdx.x * blockDim.x + threadIdx.x;
    if (i >= BATCH * ZZ) return;
    int b = i >> 7, z = i & 127;
    const float* r = g_ML + ((size_t)b << 9);
    float mj = r[z], lj = r[ZZ + z], mp = r[2 * ZZ + z], lp = r[3 * ZZ + z];
    float zj = mj + npost[i] * expf(0.5f * lj);
    float zp = mp + nprior[i] * expf(0.5f * lp);
    size_t o1 = ((size_t)b * PP + j) * ZZ + z;
    out_mpost[o1] = mj; out_lvpost[o1] = lj;
    out_mprior[o1] = mp; out_lvprior[o1] = lp;
    size_t o2 = (size_t)j * BATCH * ZZ + i;
    out_zpost[o2] = zj; out_zprior[o2] = zp;
    znext[i] = zj;
}

// ---------------- host launch ----------------
extern "C" void kernel_launch(void* const* d_in, const int* in_sizes, int n_in,
                              void* d_out, int out_size)
{
    (void)in_sizes; (void)n_in; (void)out_size;
    const float* h_i    = (const float*)d_in[0];
    const float* inpt   = (const float*)d_in[1];
    const float* npost  = (const float*)d_in[2];
    const float* nprior = (const float*)d_in[3];
    const float* W_lstm = (const float*)d_in[4];
    const float* U_lstm = (const float*)d_in[5];
    const float* b_lstm = (const float*)d_in[6];
    const float* W1 = (const float*)d_in[7];  const float* b1 = (const float*)d_in[8];
    const float* W2 = (const float*)d_in[9];  const float* b2 = (const float*)d_in[10];
    const float* W3 = (const float*)d_in[11]; const float* b3 = (const float*)d_in[12];
    const float* W4 = (const float*)d_in[13]; const float* b4 = (const float*)d_in[14];
    const float* W5 = (const float*)d_in[15]; const float* b5 = (const float*)d_in[16];
    const float* W6 = (const float*)d_in[17]; const float* b6 = (const float*)d_in[18];
    const float* W7 = (const float*)d_in[19]; const float* b7 = (const float*)d_in[20];
    const float* W8 = (const float*)d_in[21]; const float* b8 = (const float*)d_in[22];
    const float* W9 = (const float*)d_in[23]; const float* b9 = (const float*)d_in[24];
    const float* alpha = (const float*)d_in[25];
    const float* beta  = (const float*)d_in[26];
    const float* base  = (const float*)d_in[27];

    float* out = (float*)d_out;
    float* out_ys      = out;
    float* out_mpost   = out_ys + (size_t)BATCH * PP * FF;
    float* out_lvpost  = out_mpost  + (size_t)BATCH * PP * ZZ;
    float* out_mprior  = out_lvpost + (size_t)BATCH * PP * ZZ;
    float* out_lvprior = out_mprior + (size_t)BATCH * PP * ZZ;
    float* out_zpost   = out_lvprior + (size_t)BATCH * PP * ZZ;
    float* out_zprior  = out_zpost + (size_t)PP * BATCH * ZZ;
    float* out_prob    = out_zprior + (size_t)PP * BATCH * ZZ;

    float *p_Xg, *p_Wg, *p_gates, *p_Xq, *p_Wq, *p_bq, *p_HZ, *p_Wml, *p_bml,
          *p_ML, *p_hraw, *p_y1, *p_y2, *p_ybuf, *p_zbuf;
    cudaGetSymbolAddress((void**)&p_Xg, g_Xg);
    cudaGetSymbolAddress((void**)&p_Wg, g_Wg);
    cudaGetSymbolAddress((void**)&p_gates, g_gates);
    cudaGetSymbolAddress((void**)&p_Xq, g_Xq);
    cudaGetSymbolAddress((void**)&p_Wq, g_Wq);
    cudaGetSymbolAddress((void**)&p_bq, g_bq);
    cudaGetSymbolAddress((void**)&p_HZ, g_HZ);
    cudaGetSymbolAddress((void**)&p_Wml, g_Wml);
    cudaGetSymbolAddress((void**)&p_bml, g_bml);
    cudaGetSymbolAddress((void**)&p_ML, g_ML);
    cudaGetSymbolAddress((void**)&p_hraw, g_hraw);
    cudaGetSymbolAddress((void**)&p_y1, g_y1);
    cudaGetSymbolAddress((void**)&p_y2, g_y2);
    cudaGetSymbolAddress((void**)&p_ybuf, g_ybuf);
    cudaGetSymbolAddress((void**)&p_zbuf, g_zbuf);

    const int TPB = 256;
    init_state<<<(BATCH * HH + TPB - 1) / TPB, TPB>>>();
    build_weights<<<(896 * 1024 + TPB - 1) / TPB, TPB>>>(
        W_lstm, U_lstm, W4, W7, W5, W6, W8, W9, b4, b7, b5, b6, b8, b9);
    time_feat<<<(BATCH + TPB - 1) / TPB, TPB>>>(inpt, alpha, beta, base, out_prob);

    for (int j = 0; j < PP; j++) {
        int rd = j & 1, wr = 1 - rd;
        float* zprev = p_zbuf + (size_t)rd * BATCH * ZZ;
        float* znext = p_zbuf + (size_t)wr * BATCH * ZZ;
        float* yprev = p_ybuf + (size_t)rd * BATCH * FF;
        float* ycur  = p_ybuf + (size_t)wr * BATCH * FF;

        build_Xg<<<(BATCH * 896 + TPB - 1) / TPB, TPB>>>(zprev, h_i, yprev);
        sgemm2<128, 8><<<dim3(BATCH / 128, 1024 / 128), 256>>>(
            p_Xg, p_Wg, b_lstm, p_gates, 896, 1024, 0, nullptr, 0);
        lstm_pw<<<(BATCH * HH + TPB - 1) / TPB, TPB>>>(j);

        sgemm2<64, 4><<<dim3(BATCH / 64, 2), 256>>>(
            p_hraw, W1, b1, p_y1, 256, 256, 1, nullptr, 0);
        sgemm2<64, 4><<<dim3(BATCH / 64, 2), 256>>>(
            p_y1, W2, b2, p_y2, 256, 256, 1, nullptr, 0);
        sgemm2<64, 4><<<dim3(BATCH / 64, 2), 256>>>(
            p_y2, W3, b3, ycur, 256, 256, 1, out_ys, j);

        build_Xq<<<(BATCH * 1024 + TPB - 1) / TPB, TPB>>>(h_i, ycur, yprev);
        sgemm2<64, 4><<<dim3(BATCH / 64, 2), 256>>>(
            p_Xq, p_Wq, p_bq, p_HZ, 1024, 256, 1, nullptr, 0);
        sgemm2<64, 4><<<dim3(BATCH / 64, 4), 256>>>(
            p_HZ, p_Wml, p_bml, p_ML, 256, 512, 1, nullptr, 0);
        sample_out<<<(BATCH * ZZ + TPB - 1) / TPB, TPB>>>(
            npost + (size_t)j * BATCH * ZZ, nprior + (size_t)j * BATCH * ZZ,
            znext, out_mpost, out_lvpost, out_mprior, out_lvprior,
            out_zpost, out_zprior, j);
    }
}

// round 4
// speedup vs baseline: 2.1675x; 1.7883x over previous
#include <cuda_runtime.h>
#include <cuda_bf16.h>
#include <math.h>
#include <stdint.h>

#define BATCH 4096
#define TT    16
#define HH    256
#define FF    256
#define ZZ    128
#define PP    10
#define PREV_ 5

// ================= device scratch (no runtime allocation) =================
__device__ float g_gates[BATCH * 1024];
__device__ float g_c[BATCH * HH];
__device__ float g_h[BATCH * HH];
__device__ float g_hraw[BATCH * HH];
__device__ float g_ybuf[2 * BATCH * FF];
__device__ float g_zbuf[2 * BATCH * ZZ];
__device__ float g_ML[BATCH * 512];
__device__ float g_lam[PP * BATCH];
__device__ float g_bq[256];
__device__ float g_bml[512];
// bf16 hi/lo activations
__device__ __nv_bfloat16 g_Xg_h[BATCH * 896],  g_Xg_l[BATCH * 896];
__device__ __nv_bfloat16 g_hraw_h[BATCH * HH], g_hraw_l[BATCH * HH];
__device__ __nv_bfloat16 g_y1_h[BATCH * FF],   g_y1_l[BATCH * FF];
__device__ __nv_bfloat16 g_y2_h[BATCH * FF],   g_y2_l[BATCH * FF];
__device__ __nv_bfloat16 g_Xq_h[BATCH * 1024], g_Xq_l[BATCH * 1024];
__device__ __nv_bfloat16 g_HZ_h[BATCH * 256],  g_HZ_l[BATCH * 256];
// bf16 hi/lo transposed weights [N][K]
__device__ __nv_bfloat16 g_Wgt_h[1024 * 896],  g_Wgt_l[1024 * 896];
__device__ __nv_bfloat16 g_W1t_h[256 * 256],   g_W1t_l[256 * 256];
__device__ __nv_bfloat16 g_W2t_h[256 * 256],   g_W2t_l[256 * 256];
__device__ __nv_bfloat16 g_W3t_h[256 * 256],   g_W3t_l[256 * 256];
__device__ __nv_bfloat16 g_Wqt_h[256 * 1024],  g_Wqt_l[256 * 1024];
__device__ __nv_bfloat16 g_Wmlt_h[512 * 256],  g_Wmlt_l[512 * 256];

__device__ __forceinline__ void split_bf16(float x, __nv_bfloat16& h, __nv_bfloat16& l) {
    h = __float2bfloat16(x);
    l = __float2bfloat16(x - __bfloat162float(h));
}

__device__ __forceinline__ uint32_t s2u(const void* p) {
    uint32_t r;
    asm("{ .reg .u64 t; cvta.to.shared.u64 t, %1; cvt.u32.u64 %0, t; }"
        : "=r"(r) : "l"(p));
    return r;
}

__device__ __forceinline__ void ldm_x4(uint32_t& r0, uint32_t& r1,
                                       uint32_t& r2, uint32_t& r3, uint32_t a) {
    asm volatile("ldmatrix.sync.aligned.m8n8.x4.shared.b16 {%0,%1,%2,%3}, [%4];"
                 : "=r"(r0), "=r"(r1), "=r"(r2), "=r"(r3) : "r"(a));
}

__device__ __forceinline__ void mma16816(float* c, const uint32_t* a,
                                         const uint32_t* b) {
    asm volatile(
        "mma.sync.aligned.m16n8k16.row.col.f32.bf16.bf16.f32 "
        "{%0,%1,%2,%3}, {%4,%5,%6,%7}, {%8,%9}, {%0,%1,%2,%3};"
        : "+f"(c[0]), "+f"(c[1]), "+f"(c[2]), "+f"(c[3])
        : "r"(a[0]), "r"(a[1]), "r"(a[2]), "r"(a[3]), "r"(b[0]), "r"(b[1]));
}

// ================= HMMA bf16x3 GEMM =================
// C(4096 x N) = act( A(4096 x K) @ W(K x N) + bias ),  A/W as bf16 hi/lo,
// W transposed [N][K].  Block 128x128, 8 warps (2M x 4N), warp tile 64x32.
// K chunks of 32, reg-staged double-buffered smem, pitch 40 bf16 (80 B).
#define SKP   40                     // smem row pitch in bf16
#define ABYT  (128 * SKP * 2)        // 10240 B per 128x32 array
#define STG   (4 * ABYT)             // stage stride (Ah,Al,Bh,Bl)
#define DSMEM_BYTES (2 * STG)

template<int WF32, int WBF, int WYS>
__global__ __launch_bounds__(256) void hmma_gemm(
    const __nv_bfloat16* __restrict__ Ah, const __nv_bfloat16* __restrict__ Al,
    const __nv_bfloat16* __restrict__ Bh, const __nv_bfloat16* __restrict__ Bl,
    const float* __restrict__ bias, int K, int N, int relu,
    float* __restrict__ Cf, __nv_bfloat16* __restrict__ Ch,
    __nv_bfloat16* __restrict__ Cl, float* __restrict__ Cys, int jj)
{
    extern __shared__ char dsm[];
    const int tid  = threadIdx.x;
    const int wid  = tid >> 5;
    const int lane = tid & 31;
    const int wm   = wid >> 2;          // 0..1
    const int wn   = wid & 3;           // 0..3
    const int row0 = blockIdx.x * 128;
    const int col0 = blockIdx.y * 128;

    const uint32_t sb = s2u(dsm);
    const uint32_t aLane = (uint32_t)(lane & 15) * 80 + ((lane >> 4) << 4);
    const uint32_t bLane = (uint32_t)((lane & 7) + ((lane & 16) ? 8 : 0)) * 80 +
                           ((lane & 8) ? 16 : 0);

    float acc[4][4][4];
#pragma unroll
    for (int m = 0; m < 4; m++)
#pragma unroll
        for (int n = 0; n < 4; n++)
#pragma unroll
            for (int q = 0; q < 4; q++) acc[m][n][q] = 0.f;

    const int NC = K >> 5;
    const int lrow = tid >> 1;            // 0..127
    const int lcol = (tid & 1) << 4;      // 0 / 16
    const uint32_t sOff = (uint32_t)lrow * 80 + (uint32_t)lcol * 2;

    const __nv_bfloat16* gAh = Ah + (size_t)(row0 + lrow) * K + lcol;
    const __nv_bfloat16* gAl = Al + (size_t)(row0 + lrow) * K + lcol;
    const __nv_bfloat16* gBh = Bh + (size_t)(col0 + lrow) * K + lcol;
    const __nv_bfloat16* gBl = Bl + (size_t)(col0 + lrow) * K + lcol;

    // prologue: chunk 0 -> stage 0
    {
        uint4 v0, v1;
        v0 = *(const uint4*)(gAh);     v1 = *(const uint4*)(gAh + 8);
        *(uint4*)(dsm + sOff)             = v0; *(uint4*)(dsm + sOff + 16)             = v1;
        v0 = *(const uint4*)(gAl);     v1 = *(const uint4*)(gAl + 8);
        *(uint4*)(dsm + ABYT + sOff)      = v0; *(uint4*)(dsm + ABYT + sOff + 16)      = v1;
        v0 = *(const uint4*)(gBh);     v1 = *(const uint4*)(gBh + 8);
        *(uint4*)(dsm + 2 * ABYT + sOff)  = v0; *(uint4*)(dsm + 2 * ABYT + sOff + 16)  = v1;
        v0 = *(const uint4*)(gBl);     v1 = *(const uint4*)(gBl + 8);
        *(uint4*)(dsm + 3 * ABYT + sOff)  = v0; *(uint4*)(dsm + 3 * ABYT + sOff + 16)  = v1;
    }
    __syncthreads();

    for (int c = 0; c < NC; c++) {
        uint4 nAh0, nAh1, nAl0, nAl1, nBh0, nBh1, nBl0, nBl1;
        const bool more = (c + 1 < NC);
        if (more) {
            int kt = (c + 1) << 5;
            nAh0 = *(const uint4*)(gAh + kt); nAh1 = *(const uint4*)(gAh + kt + 8);
            nAl0 = *(const uint4*)(gAl + kt); nAl1 = *(const uint4*)(gAl + kt + 8);
            nBh0 = *(const uint4*)(gBh + kt); nBh1 = *(const uint4*)(gBh + kt + 8);
            nBl0 = *(const uint4*)(gBl + kt); nBl1 = *(const uint4*)(gBl + kt + 8);
        }

        const uint32_t st = sb + (uint32_t)(c & 1) * STG;
        const uint32_t pAh = st,            pAl = st + ABYT;
        const uint32_t pBh = st + 2 * ABYT, pBl = st + 3 * ABYT;

#pragma unroll
        for (int ks = 0; ks < 2; ks++) {
            const uint32_t kb = (uint32_t)ks * 32;
            uint32_t bh[4][2], bl[4][2];
#pragma unroll
            for (int nt2 = 0; nt2 < 2; nt2++) {
                uint32_t off = (uint32_t)(wn * 32 + nt2 * 16) * 80 + kb + bLane;
                ldm_x4(bh[2 * nt2][0], bh[2 * nt2][1],
                       bh[2 * nt2 + 1][0], bh[2 * nt2 + 1][1], pBh + off);
                ldm_x4(bl[2 * nt2][0], bl[2 * nt2][1],
                       bl[2 * nt2 + 1][0], bl[2 * nt2 + 1][1], pBl + off);
            }
#pragma unroll
            for (int mt = 0; mt < 4; mt++) {
                uint32_t off = (uint32_t)(wm * 64 + mt * 16) * 80 + kb + aLane;
                uint32_t ah[4], al[4];
                ldm_x4(ah[0], ah[1], ah[2], ah[3], pAh + off);
                ldm_x4(al[0], al[1], al[2], al[3], pAl + off);
#pragma unroll
                for (int nt = 0; nt < 4; nt++) {
                    mma16816(acc[mt][nt], ah, bh[nt]);
                    mma16816(acc[mt][nt], al, bh[nt]);
                    mma16816(acc[mt][nt], ah, bl[nt]);
                }
            }
        }
        __syncthreads();
        if (more) {
            char* nst = dsm + ((c + 1) & 1) * STG;
            *(uint4*)(nst + sOff)            = nAh0; *(uint4*)(nst + sOff + 16)            = nAh1;
            *(uint4*)(nst + ABYT + sOff)     = nAl0; *(uint4*)(nst + ABYT + sOff + 16)     = nAl1;
            *(uint4*)(nst + 2 * ABYT + sOff) = nBh0; *(uint4*)(nst + 2 * ABYT + sOff + 16) = nBh1;
            *(uint4*)(nst + 3 * ABYT + sOff) = nBl0; *(uint4*)(nst + 3 * ABYT + sOff + 16) = nBl1;
            __syncthreads();
        }
    }

    // epilogue
#pragma unroll
    for (int mt = 0; mt < 4; mt++) {
#pragma unroll
        for (int nt = 0; nt < 4; nt++) {
            int gc = col0 + wn * 32 + nt * 8 + (lane & 3) * 2;
            float b0 = bias[gc], b1 = bias[gc + 1];
#pragma unroll
            for (int hh = 0; hh < 2; hh++) {
                int gr = row0 + wm * 64 + mt * 16 + (lane >> 2) + hh * 8;
                float v0 = acc[mt][nt][2 * hh]     + b0;
                float v1 = acc[mt][nt][2 * hh + 1] + b1;
                if (relu) { v0 = fmaxf(v0, 0.f); v1 = fmaxf(v1, 0.f); }
                if (WF32) *(float2*)&Cf[(size_t)gr * N + gc] = make_float2(v0, v1);
                if (WBF) {
                    __nv_bfloat16 h0, l0, h1, l1;
                    split_bf16(v0, h0, l0); split_bf16(v1, h1, l1);
                    *(__nv_bfloat162*)&Ch[(size_t)gr * N + gc] = __nv_bfloat162(h0, h1);
                    *(__nv_bfloat162*)&Cl[(size_t)gr * N + gc] = __nv_bfloat162(l0, l1);
                }
                if (WYS)
                    *(float2*)&Cys[((size_t)gr * PP + jj) * N + gc] = make_float2(v0, v1);
            }
        }
    }
}

// ================= setup kernels =================
__global__ void init_state()
{
    int i = blockIdx.x * blockDim.x + threadIdx.x;
    if (i < BATCH * HH) { g_c[i] = 0.f; g_h[i] = 0.f; }
    if (i < BATCH * FF) g_ybuf[i] = 0.f;
    if (i < BATCH * ZZ) g_zbuf[i] = 0.f;
}

__global__ void build_wb(
    const float* __restrict__ W_lstm, const float* __restrict__ U_lstm,
    const float* __restrict__ W1, const float* __restrict__ W2, const float* __restrict__ W3,
    const float* __restrict__ W4, const float* __restrict__ W7,
    const float* __restrict__ W5, const float* __restrict__ W6,
    const float* __restrict__ W8, const float* __restrict__ W9,
    const float* __restrict__ b4, const float* __restrict__ b7,
    const float* __restrict__ b5, const float* __restrict__ b6,
    const float* __restrict__ b8, const float* __restrict__ b9)
{
    int i = blockIdx.x * blockDim.x + threadIdx.x;
    if (i < 1024 * 896) {                       // Wg_t[n][k]
        int n = i / 896, k = i % 896;
        float v = (k < 640) ? W_lstm[k * 1024 + n] : U_lstm[(k - 640) * 1024 + n];
        split_bf16(v, g_Wgt_h[i], g_Wgt_l[i]);
    }
    if (i < 256 * 1024) {                       // Wq_t[n][k]
        int n = i >> 10, k = i & 1023;
        float v;
        if (n < 128) v = W4[k * 128 + n];
        else {
            int cc = n - 128;
            if (k < 512)      v = W7[k * 128 + cc];
            else if (k < 768) v = 0.f;
            else              v = W7[(k - 256) * 128 + cc];
        }
        split_bf16(v, g_Wqt_h[i], g_Wqt_l[i]);
    }
    if (i < 512 * 256) {                        // Wml_t[n][k]
        int n = i >> 8, k = i & 255;
        float v = 0.f;
        if (k < 128) {
            if (n < 128)      v = W5[k * 128 + n];
            else if (n < 256) v = W6[k * 128 + (n - 128)];
        } else {
            int rr = k - 128;
            if (n >= 256 && n < 384) v = W8[rr * 128 + (n - 256)];
            else if (n >= 384)       v = W9[rr * 128 + (n - 384)];
        }
        split_bf16(v, g_Wmlt_h[i], g_Wmlt_l[i]);
    }
    if (i < 256 * 256) {                        // W1t/W2t/W3t [n][k]
        int n = i >> 8, k = i & 255;
        split_bf16(W1[k * 256 + n], g_W1t_h[i], g_W1t_l[i]);
        split_bf16(W2[k * 256 + n], g_W2t_h[i], g_W2t_l[i]);
        split_bf16(W3[k * 256 + n], g_W3t_h[i], g_W3t_l[i]);
    }
    if (i < 256) g_bq[i] = (i < 128) ? b4[i] : b7[i - 128];
    if (i < 512) {
        float v;
        if (i < 128)      v = b5[i];
        else if (i < 256) v = b6[i - 128];
        else if (i < 384) v = b8[i - 256];
        else              v = b9[i - 384];
        g_bml[i] = v;
    }
}

__global__ void time_feat(const float* __restrict__ t,
                          const float* __restrict__ alpha,
                          const float* __restrict__ beta,
                          const float* __restrict__ base,
                          float* __restrict__ out_prob)
{
    int b = blockIdx.x * blockDim.x + threadIdx.x;
    if (b >= BATCH) return;
    float al = *alpha, be = *beta, ba = *base;
    float tv[TT];
#pragma unroll
    for (int i = 0; i < TT; i++) tv[i] = t[b * TT + i];
#pragma unroll
    for (int j = 0; j < PP; j++) {
        int cti = PREV_ + j;
        float ct = tv[cti], last = tv[cti - 1];
        float tk = 0.f, td = 0.f;
        for (int i = 0; i < cti; i++) {
            tk += expf(be * (tv[i] - ct));
            td += expf(be * (tv[i] - last));
        }
        float lm = ba + al * tk;
        g_lam[j * BATCH + b] = lm;
        out_prob[j * BATCH + b] = lm * expf((last - ct) * ba + (al / be) * (tk - td));
    }
}

// ================= per-step elementwise =================
__global__ void build_Xg(const float* __restrict__ zprev,
                         const float* __restrict__ hi,
                         const float* __restrict__ yprev)
{
    int i = blockIdx.x * blockDim.x + threadIdx.x;
    if (i >= BATCH * 896) return;
    int b = i / 896, c = i % 896;
    float v;
    if (c < 128)       v = zprev[(b << 7) + c];
    else if (c < 384)  v = hi[(b << 8) + (c - 128)];
    else if (c < 640)  v = yprev[(b << 8) + (c - 384)];
    else               v = g_h[(b << 8) + (c - 640)];
    split_bf16(v, g_Xg_h[i], g_Xg_l[i]);
}

__device__ __forceinline__ float sigm(float x) { return 1.f / (1.f + expf(-x)); }

__global__ void lstm_pw(int j)
{
    int i = blockIdx.x * blockDim.x + threadIdx.x;
    if (i >= BATCH * HH) return;
    int b = i >> 8, k = i & 255;
    const float* g = g_gates + ((size_t)b << 10);
    float gi = g[k], gf = g[HH + k], gg = g[2 * HH + k], go = g[3 * HH + k];
    float cv = sigm(gf) * g_c[i] + sigm(gi) * tanhf(gg);
    g_c[i] = cv;
    float hr = sigm(go) * tanhf(cv);
    g_hraw[i] = hr;
    split_bf16(hr, g_hraw_h[i], g_hraw_l[i]);
    g_h[i] = g_lam[j * BATCH + b] * hr;
}

__global__ void build_Xq(const float* __restrict__ hi,
                         const float* __restrict__ ycur,
                         const float* __restrict__ yprev)
{
    int i = blockIdx.x * blockDim.x + threadIdx.x;
    if (i >= BATCH * 1024) return;
    int b = i >> 10, c = i & 1023;
    float v;
    if (c < 256)       v = hi[(b << 8) + c];
    else if (c < 512)  v = g_hraw[(b << 8) + (c - 256)];
    else if (c < 768)  v = ycur[(b << 8) + (c - 512)];
    else               v = yprev[(b << 8) + (c - 768)];
    split_bf16(v, g_Xq_h[i], g_Xq_l[i]);
}

__global__ void sample_out(const float* __restrict__ npost,
                           const float* __restrict__ nprior,
                           float* __restrict__ znext,
                           float* __restrict__ out_mpost, float* __restrict__ out_lvpost,
                           float* __restrict__ out_mprior, float* __restrict__ out_lvprior,
                           float* __restrict__ out_zpost, float* __restrict__ out_zprior,
                           int j)
{
    int i = blockIdx.x * blockDim.x + threadIdx.x;
    if (i >= BATCH * ZZ) return;
    int b = i >> 7, z = i & 127;
    const float* r = g_ML + ((size_t)b << 9);
    float mj = r[z], lj = r[ZZ + z], mp = r[2 * ZZ + z], lp = r[3 * ZZ + z];
    float zj = mj + npost[i] * expf(0.5f * lj);
    float zp = mp + nprior[i] * expf(0.5f * lp);
    size_t o1 = ((size_t)b * PP + j) * ZZ + z;
    out_mpost[o1] = mj;  out_lvpost[o1] = lj;
    out_mprior[o1] = mp; out_lvprior[o1] = lp;
    size_t o2 = (size_t)j * BATCH * ZZ + i;
    out_zpost[o2] = zj;  out_zprior[o2] = zp;
    znext[i] = zj;
}

// ================= host launch =================
template<typename T>
static T* sym(const void* s) { void* p; cudaGetSymbolAddress(&p, s); return (T*)p; }

extern "C" void kernel_launch(void* const* d_in, const int* in_sizes, int n_in,
                              void* d_out, int out_size)
{
    (void)in_sizes; (void)n_in; (void)out_size;
    const float* h_i    = (const float*)d_in[0];
    const float* inpt   = (const float*)d_in[1];
    const float* npost  = (const float*)d_in[2];
    const float* nprior = (const float*)d_in[3];
    const float* W_lstm = (const float*)d_in[4];
    const float* U_lstm = (const float*)d_in[5];
    const float* b_lstm = (const float*)d_in[6];
    const float* W1 = (const float*)d_in[7];  const float* b1 = (const float*)d_in[8];
    const float* W2 = (const float*)d_in[9];  const float* b2 = (const float*)d_in[10];
    const float* W3 = (const float*)d_in[11]; const float* b3 = (const float*)d_in[12];
    const float* W4 = (const float*)d_in[13]; const float* b4 = (const float*)d_in[14];
    const float* W5 = (const float*)d_in[15]; const float* b5 = (const float*)d_in[16];
    const float* W6 = (const float*)d_in[17]; const float* b6 = (const float*)d_in[18];
    const float* W7 = (const float*)d_in[19]; const float* b7 = (const float*)d_in[20];
    const float* W8 = (const float*)d_in[21]; const float* b8 = (const float*)d_in[22];
    const float* W9 = (const float*)d_in[23]; const float* b9 = (const float*)d_in[24];
    const float* alpha = (const float*)d_in[25];
    const float* beta  = (const float*)d_in[26];
    const float* base  = (const float*)d_in[27];

    float* out = (float*)d_out;
    float* out_ys      = out;
    float* out_mpost   = out_ys + (size_t)BATCH * PP * FF;
    float* out_lvpost  = out_mpost  + (size_t)BATCH * PP * ZZ;
    float* out_mprior  = out_lvpost + (size_t)BATCH * PP * ZZ;
    float* out_lvprior = out_mprior + (size_t)BATCH * PP * ZZ;
    float* out_zpost   = out_lvprior + (size_t)BATCH * PP * ZZ;
    float* out_zprior  = out_zpost + (size_t)PP * BATCH * ZZ;
    float* out_prob    = out_zprior + (size_t)PP * BATCH * ZZ;

    float* p_gates = sym<float>(g_gates);
    float* p_ML    = sym<float>(g_ML);
    float* p_ybuf  = sym<float>(g_ybuf);
    float* p_zbuf  = sym<float>(g_zbuf);
    float* p_bq    = sym<float>(g_bq);
    float* p_bml   = sym<float>(g_bml);
    __nv_bfloat16* p_Xg_h  = sym<__nv_bfloat16>(g_Xg_h);
    __nv_bfloat16* p_Xg_l  = sym<__nv_bfloat16>(g_Xg_l);
    __nv_bfloat16* p_hr_h  = sym<__nv_bfloat16>(g_hraw_h);
    __nv_bfloat16* p_hr_l  = sym<__nv_bfloat16>(g_hraw_l);
    __nv_bfloat16* p_y1_h  = sym<__nv_bfloat16>(g_y1_h);
    __nv_bfloat16* p_y1_l  = sym<__nv_bfloat16>(g_y1_l);
    __nv_bfloat16* p_y2_h  = sym<__nv_bfloat16>(g_y2_h);
    __nv_bfloat16* p_y2_l  = sym<__nv_bfloat16>(g_y2_l);
    __nv_bfloat16* p_Xq_h  = sym<__nv_bfloat16>(g_Xq_h);
    __nv_bfloat16* p_Xq_l  = sym<__nv_bfloat16>(g_Xq_l);
    __nv_bfloat16* p_HZ_h  = sym<__nv_bfloat16>(g_HZ_h);
    __nv_bfloat16* p_HZ_l  = sym<__nv_bfloat16>(g_HZ_l);
    __nv_bfloat16* p_Wgt_h = sym<__nv_bfloat16>(g_Wgt_h);
    __nv_bfloat16* p_Wgt_l = sym<__nv_bfloat16>(g_Wgt_l);
    __nv_bfloat16* p_W1t_h = sym<__nv_bfloat16>(g_W1t_h);
    __nv_bfloat16* p_W1t_l = sym<__nv_bfloat16>(g_W1t_l);
    __nv_bfloat16* p_W2t_h = sym<__nv_bfloat16>(g_W2t_h);
    __nv_bfloat16* p_W2t_l = sym<__nv_bfloat16>(g_W2t_l);
    __nv_bfloat16* p_W3t_h = sym<__nv_bfloat16>(g_W3t_h);
    __nv_bfloat16* p_W3t_l = sym<__nv_bfloat16>(g_W3t_l);
    __nv_bfloat16* p_Wqt_h = sym<__nv_bfloat16>(g_Wqt_h);
    __nv_bfloat16* p_Wqt_l = sym<__nv_bfloat16>(g_Wqt_l);
    __nv_bfloat16* p_Wmlt_h = sym<__nv_bfloat16>(g_Wmlt_h);
    __nv_bfloat16* p_Wmlt_l = sym<__nv_bfloat16>(g_Wmlt_l);

    cudaFuncSetAttribute(hmma_gemm<1,0,0>, cudaFuncAttributeMaxDynamicSharedMemorySize, DSMEM_BYTES);
    cudaFuncSetAttribute(hmma_gemm<0,1,0>, cudaFuncAttributeMaxDynamicSharedMemorySize, DSMEM_BYTES);
    cudaFuncSetAttribute(hmma_gemm<1,0,1>, cudaFuncAttributeMaxDynamicSharedMemorySize, DSMEM_BYTES);

    const int TPB = 256;
    init_state<<<(BATCH * HH + TPB - 1) / TPB, TPB>>>();
    build_wb<<<(1024 * 896 + TPB - 1) / TPB, TPB>>>(
        W_lstm, U_lstm, W1, W2, W3, W4, W7, W5, W6, W8, W9,
        b4, b7, b5, b6, b8, b9);
    time_feat<<<(BATCH + TPB - 1) / TPB, TPB>>>(inpt, alpha, beta, base, out_prob);

    for (int j = 0; j < PP; j++) {
        int rd = j & 1, wr = 1 - rd;
        float* zprev = p_zbuf + (size_t)rd * BATCH * ZZ;
        float* znext = p_zbuf + (size_t)wr * BATCH * ZZ;
        float* yprev = p_ybuf + (size_t)rd * BATCH * FF;
        float* ycur  = p_ybuf + (size_t)wr * BATCH * FF;

        build_Xg<<<(BATCH * 896 + TPB - 1) / TPB, TPB>>>(zprev, h_i, yprev);
        hmma_gemm<1,0,0><<<dim3(32, 8), 256, DSMEM_BYTES>>>(
            p_Xg_h, p_Xg_l, p_Wgt_h, p_Wgt_l, b_lstm, 896, 1024, 0,
            p_gates, nullptr, nullptr, nullptr, 0);
        lstm_pw<<<(BATCH * HH + TPB - 1) / TPB, TPB>>>(j);

        hmma_gemm<0,1,0><<<dim3(32, 2), 256, DSMEM_BYTES>>>(
            p_hr_h, p_hr_l, p_W1t_h, p_W1t_l, b1, 256, 256, 1,
            nullptr, p_y1_h, p_y1_l, nullptr, 0);
        hmma_gemm<0,1,0><<<dim3(32, 2), 256, DSMEM_BYTES>>>(
            p_y1_h, p_y1_l, p_W2t_h, p_W2t_l, b2, 256, 256, 1,
            nullptr, p_y2_h, p_y2_l, nullptr, 0);
        hmma_gemm<1,0,1><<<dim3(32, 2), 256, DSMEM_BYTES>>>(
            p_y2_h, p_y2_l, p_W3t_h, p_W3t_l, b3, 256, 256, 1,
            ycur, nullptr, nullptr, out_ys, j);

        build_Xq<<<(BATCH * 1024 + TPB - 1) / TPB, TPB>>>(h_i, ycur, yprev);
        hmma_gemm<0,1,0><<<dim3(32, 2), 256, DSMEM_BYTES>>>(
            p_Xq_h, p_Xq_l, p_Wqt_h, p_Wqt_l, p_bq, 1024, 256, 1,
            nullptr, p_HZ_h, p_HZ_l, nullptr, 0);
        hmma_gemm<1,0,0><<<dim3(32, 4), 256, DSMEM_BYTES>>>(
            p_HZ_h, p_HZ_l, p_Wmlt_h, p_Wmlt_l, p_bml, 256, 512, 1,
            p_ML, nullptr, nullptr, nullptr, 0);
        sample_out<<<(BATCH * ZZ + TPB - 1) / TPB, TPB>>>(
            npost + (size_t)j * BATCH * ZZ, nprior + (size_t)j * BATCH * ZZ,
            znext, out_mpost, out_lvpost, out_mprior, out_lvprior,
            out_zpost, out_zprior, j);
    }
}